// round 3
// baseline (speedup 1.0000x reference)
#include <cuda_runtime.h>

// Problem constants: x [B=8, I=32, O=32, D=8, H=14, W=14, kh=3, kw=3] fp32
// out [B, O, D, H, W] fp32
namespace {
constexpr int Bn = 8, In = 32, On = 32, Dn = 8, Hn = 14, Wn = 14, Kn = 9;
constexpr int WK   = Wn * Kn;   // 126 contiguous floats per (b,i,o,d,h)
constexpr int SLAB = Dn * WK;   // 1008 floats = 4032 B per (b,i,o,h) slab
constexpr int NT   = 256;
constexpr int SUBK = 26;        // ceil(0.8 * 32)
}

__device__ __forceinline__ void cp_async8(void* sm, const void* gm) {
    unsigned s = (unsigned)__cvta_generic_to_shared(sm);
    asm volatile("cp.async.ca.shared.global [%0], [%1], 8;\n" :: "r"(s), "l"(gm));
}
__device__ __forceinline__ void cp_commit() {
    asm volatile("cp.async.commit_group;\n");
}
template <int N>
__device__ __forceinline__ void cp_wait() {
    asm volatile("cp.async.wait_group %0;\n" :: "n"(N));
}

// single-MUFU approximate math (rel err ~2^-23, far inside 1e-3 budget)
__device__ __forceinline__ float fsqrt_ap(float x) {
    float r; asm("sqrt.approx.f32 %0, %1;" : "=f"(r) : "f"(x)); return r;
}
__device__ __forceinline__ float frcp_ap(float x) {
    float r; asm("rcp.approx.f32 %0, %1;" : "=f"(r) : "f"(x)); return r;
}

// Monotone float -> uint key: a <= b  <=>  fkey(a) <= fkey(b)
__device__ __forceinline__ unsigned fkey(float f) {
    unsigned u = __float_as_uint(f);
    return u ^ (unsigned)(((int)u >> 31) | 0x80000000);
}

__global__ void __launch_bounds__(NT)
caps_route_kernel(const float* __restrict__ x, float* __restrict__ out) {
    const int h = blockIdx.x, o = blockIdx.y, b = blockIdx.z;
    const int tid = threadIdx.x;

    __shared__ __align__(16) float sl[2][SLAB];   // double-buffered input slab
    __shared__ float    sNorm[WK];                 // per-(w,k) norm over D
    __shared__ float    sRden[Wn];                 // 1 / sum_k norm, per w
    __shared__ float    sXavg[In * Dn * Wn];       // [i][d][w]
    __shared__ float    sNI[In * Wn];              // [i][w]
    __shared__ float    sRsum[Wn];                 // 1 / sum_i nI, per w
    __shared__ float    sV[Dn * Wn];               // consensus [d][w]
    __shared__ float    sLoss[In * Wn];            // [i][w]
    __shared__ unsigned sThr[Wn];                  // threshold keys per w
    __shared__ float    sRfin[Wn];                 // 1 / masked sum_i nI, per w

    const long strideD = (long)Hn * Wn * Kn;       // 1764
    const long strideO = Dn * strideD;             // 14112
    const long strideI = On * strideO;             // 451584
    const long strideB = In * strideI;             // 14450688
    const float* base = x + (long)b * strideB + (long)o * strideO + (long)h * WK;

    // ---- hoisted per-thread load offsets (8B granules; SLAB/2 = 504 of them) ----
    const int j0 = tid, j1 = tid + NT;
    const int d0 = j0 / 63, c0 = j0 - 63 * d0;
    const int sOff0 = d0 * WK + 2 * c0;
    const long gOff0 = (long)d0 * strideD + 2 * c0;
    const bool has1 = (j1 < SLAB / 2);
    const int d1 = j1 / 63, c1 = j1 - 63 * d1;
    const int sOff1 = d1 * WK + 2 * c1;
    const long gOff1 = (long)d1 * strideD + 2 * c1;

    // ---- hoisted compute-phase coordinates ----
    // Region A: 224 threads = warps 0..6; groups of 16 lanes per w (9 real)
    const int wA = tid >> 4, kA = tid & 15;
    const bool actA  = (tid < 224);
    const bool realA = actA && (kA < Kn);
    const int wkA = wA * Kn + kA;
    // Region C: 112 threads, one per (d, w)
    const bool actC = (tid < Dn * Wn);
    const int dC = tid / Wn, wC = tid - dC * Wn;

    // ---- prefetch slab i = 0 ----
    cp_async8(&sl[0][sOff0], base + gOff0);
    if (has1) cp_async8(&sl[0][sOff1], base + gOff1);
    cp_commit();
    if (tid < Wn) sThr[tid] = 0u;

    // ---- Phase 1: per input capsule, kernel-position weighted average ----
    for (int i = 0; i < In; ++i) {
        const int cur = i & 1;
        if (i + 1 < In) {
            const float* g = base + (long)(i + 1) * strideI;
            float* dst = sl[cur ^ 1];
            cp_async8(&dst[sOff0], g + gOff0);
            if (has1) cp_async8(&dst[sOff1], g + gOff1);
            cp_commit();
            cp_wait<1>();   // current buffer's group complete
        } else {
            cp_wait<0>();
        }
        __syncthreads();

        const float* s = sl[cur];

        // A: norms over D per (w,k) + per-w denominator via shfl reduction
        if (actA) {
            float nv = 0.f;
            if (realA) {
                float ss = 0.f;
                #pragma unroll
                for (int d = 0; d < Dn; ++d) {
                    float v = s[d * WK + wkA];
                    ss += v * v;
                }
                nv = fsqrt_ap(ss);
                sNorm[wkA] = nv;
            }
            float sum = nv;
            sum += __shfl_xor_sync(0xffffffffu, sum, 8, 16);
            sum += __shfl_xor_sync(0xffffffffu, sum, 4, 16);
            sum += __shfl_xor_sync(0xffffffffu, sum, 2, 16);
            sum += __shfl_xor_sync(0xffffffffu, sum, 1, 16);
            if (kA == 0) sRden[wA] = frcp_ap(sum);
        }
        __syncthreads();

        // C: xavg[d][w] = (sum_k n_k * x) * (1/sum_k n_k)
        if (actC) {
            const float* sn = &sNorm[wC * Kn];
            const float* sx = &s[dC * WK + wC * Kn];
            float num = 0.f;
            #pragma unroll
            for (int k = 0; k < Kn; ++k)
                num += sn[k] * sx[k];
            sXavg[(i * Dn + dC) * Wn + wC] = num * sRden[wC];
        }
        __syncthreads();
    }

    // ---- Phase 2: reductions over input capsules (all SMEM) ----
    // nI[i][w] = || xavg[i,:,w] ||
    for (int p = tid; p < In * Wn; p += NT) {
        int i = p / Wn, w = p - Wn * i;
        float acc = 0.f;
        #pragma unroll
        for (int d = 0; d < Dn; ++d) {
            float v = sXavg[(i * Dn + d) * Wn + w];
            acc += v * v;
        }
        sNI[p] = fsqrt_ap(acc);
    }
    __syncthreads();

    if (tid < Wn) {
        float sum = 0.f;
        #pragma unroll 4
        for (int i = 0; i < In; ++i) sum += sNI[i * Wn + tid];
        sRsum[tid] = frcp_ap(sum);
    }
    __syncthreads();

    // consensus v[d][w]
    if (actC) {
        float num = 0.f;
        #pragma unroll 4
        for (int i = 0; i < In; ++i)
            num += sNI[i * Wn + wC] * sXavg[(i * Dn + dC) * Wn + wC];
        sV[dC * Wn + wC] = num * sRsum[wC];
    }
    __syncthreads();

    // losses[i][w] = -<v[:, w], xavg[i,:,w]>
    for (int p = tid; p < In * Wn; p += NT) {
        int i = p / Wn, w = p - Wn * i;
        float acc = 0.f;
        #pragma unroll
        for (int d = 0; d < Dn; ++d)
            acc += sV[d * Wn + w] * sXavg[(i * Dn + d) * Wn + w];
        sLoss[p] = -acc;
    }
    __syncthreads();

    // kth-smallest threshold (k = SUBK), exact tie semantics:
    // thr = max{ v : #(x < v) <= SUBK-1 } == sorted[SUBK-1]
    for (int p = tid; p < In * Wn; p += NT) {
        int i = p / Wn, w = p - Wn * i;
        float mine = sLoss[p];
        int cnt = 0;
        #pragma unroll 8
        for (int j = 0; j < In; ++j)
            cnt += (sLoss[j * Wn + w] < mine);
        if (cnt <= SUBK - 1)
            atomicMax(&sThr[w], fkey(mine));
    }
    __syncthreads();

    // masked denominator reciprocal per w
    if (tid < Wn) {
        const unsigned thr = sThr[tid];
        float den = 0.f;
        #pragma unroll 4
        for (int i = 0; i < In; ++i)
            if (fkey(sLoss[i * Wn + tid]) <= thr) den += sNI[i * Wn + tid];
        sRfin[tid] = frcp_ap(den);
    }
    __syncthreads();

    // masked re-average, write output
    if (actC) {
        const unsigned thr = sThr[wC];
        float num = 0.f;
        #pragma unroll 4
        for (int i = 0; i < In; ++i) {
            if (fkey(sLoss[i * Wn + wC]) <= thr)
                num += sNI[i * Wn + wC] * sXavg[(i * Dn + dC) * Wn + wC];
        }
        out[(((long)b * On + o) * Dn + dC) * (Hn * Wn) + h * Wn + wC] = num * sRfin[wC];
    }
}

extern "C" void kernel_launch(void* const* d_in, const int* in_sizes, int n_in,
                              void* d_out, int out_size) {
    const float* x = (const float*)d_in[0];
    float* out = (float*)d_out;
    dim3 grid(Hn, On, Bn);   // 14 x 32 x 8 = 3584 CTAs
    caps_route_kernel<<<grid, NT>>>(x, out);
}